// round 5
// baseline (speedup 1.0000x reference)
#include <cuda_runtime.h>

// Aggregation: out[n, g*32+wc, h, w] =
//   sum_{kh,kw} x_reflect[n, g*32+wc, h+kh-1, w+kw-1] * weight[n, wc, kh*3+kw, h, w]
//
// x (8,256,128,128) f32, weight (8,32,9,128,128) f32, out = x shape.
//
// Traffic is at the algorithmic floor; limiter is DRAM-busy% (78 in R4).
// R5: split the 8-group loop into 2 chunks of 4 to cut registers 80 -> ~60,
// enabling 4 CTAs/SM (32 warps vs 22). Weight float4s are re-read in chunk 2
// but hit L1/L2 (same thread, tiny reuse distance) -> no extra DRAM traffic.
// Halo columns via warp shuffle (a warp spans one full row of 128).

namespace {
constexpr int N  = 8;
constexpr int C  = 256;
constexpr int H  = 128;
constexpr int W  = 128;
constexpr int WC = 32;
constexpr int G  = C / WC;   // 8
constexpr int GC = 4;        // groups per chunk
constexpr int HW = H * W;
}

__global__ __launch_bounds__(256, 4)
void agg_kernel(const float* __restrict__ x,
                const float* __restrict__ wt,
                float* __restrict__ out)
{
    const int tid = blockIdx.x * 256 + threadIdx.x;
    // Decode: w4 (32) fastest -> lane id == w4; then h (128), wc (32), n (8)
    const int w4 = tid & 31;
    const int h  = (tid >> 5) & 127;
    const int wc = (tid >> 12) & 31;
    const int n  = tid >> 17;
    const int w  = w4 << 2;

    // Reflect rows (PAD=1: only -1 and 128 occur)
    const int hr0 = (h == 0)     ? 1     : h - 1;
    const int hr2 = (h == H - 1) ? H - 2 : h + 1;
    const int rows[3] = { hr0, h, hr2 };

    const bool lane_lo = (w4 == 0);
    const bool lane_hi = (w4 == 31);

    const size_t x_n_base = (size_t)n * C * HW;
    const float* xbase = x + x_n_base + (size_t)wc * HW + w;
    float*       obase = out + x_n_base + (size_t)wc * HW + (size_t)h * W + w;

    const float4* wp = reinterpret_cast<const float4*>(
        wt + ((size_t)(n * WC + wc) * 9) * HW + (size_t)h * W + w);

    #pragma unroll
    for (int gc = 0; gc < G / GC; gc++) {
        const float* xchunk = xbase + (size_t)(gc * GC * WC) * HW;

        float4 acc[GC];
        #pragma unroll
        for (int g = 0; g < GC; g++)
            acc[g] = make_float4(0.f, 0.f, 0.f, 0.f);

        #pragma unroll
        for (int kh = 0; kh < 3; kh++) {
            // 3 weight float4s (cached: chunk 2 re-reads them from L1/L2)
            const float4 wA = __ldg(wp + (kh * 3 + 0) * (HW / 4));
            const float4 wB = __ldg(wp + (kh * 3 + 1) * (HW / 4));
            const float4 wD = __ldg(wp + (kh * 3 + 2) * (HW / 4));

            // 4 independent x-row loads, batched back-to-back
            const float* xr = xchunk + rows[kh] * W;
            float4 xm[GC];
            #pragma unroll
            for (int g = 0; g < GC; g++)
                xm[g] = *reinterpret_cast<const float4*>(xr + g * (WC * HW));

            #pragma unroll
            for (int g = 0; g < GC; g++) {
                const float v1 = xm[g].x, v2 = xm[g].y,
                            v3 = xm[g].z, v4 = xm[g].w;
                // halo via warp shuffle; reflect at row ends is intra-lane
                float v0 = __shfl_up_sync(0xffffffffu, v4, 1);
                float v5 = __shfl_down_sync(0xffffffffu, v1, 1);
                if (lane_lo) v0 = v2;   // col -1  -> col 1
                if (lane_hi) v5 = v3;   // col 128 -> col 126

                acc[g].x = fmaf(v0, wA.x, fmaf(v1, wB.x, fmaf(v2, wD.x, acc[g].x)));
                acc[g].y = fmaf(v1, wA.y, fmaf(v2, wB.y, fmaf(v3, wD.y, acc[g].y)));
                acc[g].z = fmaf(v2, wA.z, fmaf(v3, wB.z, fmaf(v4, wD.z, acc[g].z)));
                acc[g].w = fmaf(v3, wA.w, fmaf(v4, wB.w, fmaf(v5, wD.w, acc[g].w)));
            }
        }

        // contiguous write burst for this chunk: 4 streaming float4 stores
        float* ob = obase + (size_t)(gc * GC * WC) * HW;
        #pragma unroll
        for (int g = 0; g < GC; g++)
            __stcs(reinterpret_cast<float4*>(ob + g * (WC * HW)), acc[g]);
    }
}

extern "C" void kernel_launch(void* const* d_in, const int* in_sizes, int n_in,
                              void* d_out, int out_size)
{
    const float* x  = (const float*)d_in[0];
    const float* wt = (const float*)d_in[1];
    float* out      = (float*)d_out;

    const int total   = N * WC * H * (W / 4);  // 1,048,576 threads
    const int threads = 256;
    const int blocks  = total / threads;       // 4096
    agg_kernel<<<blocks, threads>>>(x, wt, out);
}

// round 6
// speedup vs baseline: 1.0099x; 1.0099x over previous
#include <cuda_runtime.h>

// Aggregation: out[n, g*32+wc, h, w] =
//   sum_{kh,kw} x_reflect[n, g*32+wc, h+kh-1, w+kw-1] * weight[n, wc, kh*3+kw, h, w]
//
// x (8,256,128,128) f32, weight (8,32,9,128,128) f32, out = x shape.
//
// Traffic is at the algorithmic floor (~390MB); limiter is DRAM-busy%.
// R4 (best, 78% busy): per-kh phases of [11 loads][FMA drain] leave DRAM idle
// during drains. R6 software-pipelines across kh: kh+1's 3 weight + 8 x loads
// are issued BEFORE kh's FMA block, so every compute phase overlaps a fresh
// load batch. 2 CTAs/SM (128-reg budget) to hold both load generations live.
// R5 lesson: per-warp MLP depth beats warp count on this kernel.

namespace {
constexpr int N  = 8;
constexpr int C  = 256;
constexpr int H  = 128;
constexpr int W  = 128;
constexpr int WC = 32;
constexpr int G  = C / WC;   // 8
constexpr int HW = H * W;
constexpr int CS = WC * HW;  // channel-group stride in elements
}

__global__ __launch_bounds__(256, 2)
void agg_kernel(const float* __restrict__ x,
                const float* __restrict__ wt,
                float* __restrict__ out)
{
    const int tid = blockIdx.x * 256 + threadIdx.x;
    // Decode: w4 (32) fastest -> lane id == w4; then h (128), wc (32), n (8)
    const int w4 = tid & 31;
    const int h  = (tid >> 5) & 127;
    const int wc = (tid >> 12) & 31;
    const int n  = tid >> 17;
    const int w  = w4 << 2;

    // Reflect rows (PAD=1: only -1 and 128 occur)
    const int hr0 = (h == 0)     ? 1     : h - 1;
    const int hr2 = (h == H - 1) ? H - 2 : h + 1;
    const int rows[3] = { hr0, h, hr2 };

    const bool lane_lo = (w4 == 0);
    const bool lane_hi = (w4 == 31);

    const size_t x_n_base = (size_t)n * C * HW;
    const float* xbase = x + x_n_base + (size_t)wc * HW + w;

    const float4* wp = reinterpret_cast<const float4*>(
        wt + ((size_t)(n * WC + wc) * 9) * HW + (size_t)h * W + w);

    float4 acc[G];
    #pragma unroll
    for (int g = 0; g < G; g++)
        acc[g] = make_float4(0.f, 0.f, 0.f, 0.f);

    // Two load generations (cur/next); full unroll lets ptxas rename.
    float4 wv[2][3];
    float4 xm[2][G];

    // ---- Prologue: issue kh=0 batch ----
    {
        #pragma unroll
        for (int j = 0; j < 3; j++)
            wv[0][j] = __ldcs(wp + j * (HW / 4));
        const float* xr = xbase + rows[0] * W;
        #pragma unroll
        for (int g = 0; g < G; g++)
            xm[0][g] = *reinterpret_cast<const float4*>(xr + g * CS);
    }

    #pragma unroll
    for (int kh = 0; kh < 3; kh++) {
        const int cur = kh & 1;
        const int nxt = cur ^ 1;

        // ---- Issue next kh's batch before consuming current ----
        if (kh < 2) {
            #pragma unroll
            for (int j = 0; j < 3; j++)
                wv[nxt][j] = __ldcs(wp + ((kh + 1) * 3 + j) * (HW / 4));
            const float* xr = xbase + rows[kh + 1] * W;
            #pragma unroll
            for (int g = 0; g < G; g++)
                xm[nxt][g] = *reinterpret_cast<const float4*>(xr + g * CS);
        }

        // ---- Consume current batch ----
        const float4 wA = wv[cur][0];
        const float4 wB = wv[cur][1];
        const float4 wD = wv[cur][2];

        #pragma unroll
        for (int g = 0; g < G; g++) {
            const float v1 = xm[cur][g].x, v2 = xm[cur][g].y,
                        v3 = xm[cur][g].z, v4 = xm[cur][g].w;
            // halo via warp shuffle; reflect at row ends is intra-lane
            float v0 = __shfl_up_sync(0xffffffffu, v4, 1);
            float v5 = __shfl_down_sync(0xffffffffu, v1, 1);
            if (lane_lo) v0 = v2;   // col -1  -> col 1
            if (lane_hi) v5 = v3;   // col 128 -> col 126

            acc[g].x = fmaf(v0, wA.x, fmaf(v1, wB.x, fmaf(v2, wD.x, acc[g].x)));
            acc[g].y = fmaf(v1, wA.y, fmaf(v2, wB.y, fmaf(v3, wD.y, acc[g].y)));
            acc[g].z = fmaf(v2, wA.z, fmaf(v3, wB.z, fmaf(v4, wD.z, acc[g].z)));
            acc[g].w = fmaf(v3, wA.w, fmaf(v4, wB.w, fmaf(v5, wD.w, acc[g].w)));
        }
    }

    // One contiguous write burst: 8 streaming float4 stores
    float* ob = out + x_n_base + (size_t)wc * HW + (size_t)h * W + w;
    #pragma unroll
    for (int g = 0; g < G; g++)
        __stcs(reinterpret_cast<float4*>(ob + g * CS), acc[g]);
}

extern "C" void kernel_launch(void* const* d_in, const int* in_sizes, int n_in,
                              void* d_out, int out_size)
{
    const float* x  = (const float*)d_in[0];
    const float* wt = (const float*)d_in[1];
    float* out      = (float*)d_out;

    const int total   = N * WC * H * (W / 4);  // 1,048,576 threads
    const int threads = 256;
    const int blocks  = total / threads;       // 4096
    agg_kernel<<<blocks, threads>>>(x, wt, out);
}